// round 6
// baseline (speedup 1.0000x reference)
#include <cuda_runtime.h>

#define NN 100000
#define NE 1600000
#define DIM 128
#define DC 64
#define BN_EPS 1e-5f

// ---------------- scratch (device globals; no allocation allowed) ----------
__device__ float g_buf_agg[NN * DIM];   // aggregation buffer / layer-3 g [N,64]
__device__ float g_buf_h[NN * DIM];     // hidden activations
__device__ float g_norm_src[NN];
__device__ float g_norm_dst[NN];
__device__ int   g_deg_out[NN];
__device__ int   g_deg_in[NN];
__device__ float g_sum[DIM];
__device__ float g_sumsq[DIM];
__device__ float g_mean[DIM];
__device__ float g_rstd[DIM];

// buffer selector: avoids any host-side cudaGetSymbolAddress during capture
#define BUF_AGG 0
#define BUF_H   1
__device__ __forceinline__ float* buf_sel(int s) {
    return (s == BUF_AGG) ? g_buf_agg : g_buf_h;
}

// ---------------- degree / norm kernels ------------------------------------
__global__ void k_init_deg() {
    int i = blockIdx.x * blockDim.x + threadIdx.x;
    if (i < NN) { g_deg_out[i] = 0; g_deg_in[i] = 0; }
}

__global__ void k_count(const int* __restrict__ src, const int* __restrict__ dst) {
    int e = blockIdx.x * blockDim.x + threadIdx.x;
    if (e < NE) {
        atomicAdd(&g_deg_out[src[e]], 1);
        atomicAdd(&g_deg_in[dst[e]], 1);
    }
}

__global__ void k_norms() {
    int i = blockIdx.x * blockDim.x + threadIdx.x;
    if (i < NN) {
        g_norm_src[i] = rsqrtf(fmaxf((float)g_deg_out[i], 1.0f));
        g_norm_dst[i] = rsqrtf(fmaxf((float)g_deg_in[i], 1.0f));
    }
}

// ---------------- zero kernels ----------------------------------------------
__global__ void k_zero_agg(int n4) {
    int i = blockIdx.x * blockDim.x + threadIdx.x;
    if (i < n4) reinterpret_cast<float4*>(g_buf_agg)[i] = make_float4(0.f, 0.f, 0.f, 0.f);
}

__global__ void k_zero_out(float* __restrict__ p, int n4) {
    int i = blockIdx.x * blockDim.x + threadIdx.x;
    if (i < n4) reinterpret_cast<float4*>(p)[i] = make_float4(0.f, 0.f, 0.f, 0.f);
}

__global__ void k_zero_stats() {
    int i = threadIdx.x;
    if (i < DIM) { g_sum[i] = 0.f; g_sumsq[i] = 0.f; }
}

// ---------------- SpMM (gather + vector-RED scatter) ------------------------
// one warp per edge, 128 feats = 32 lanes x float4
// SRC_SEL: -1 => external pointer (features); else internal buffer selector.
template<int SRC_SEL, bool BN>
__global__ void k_spmm128(const float* __restrict__ hext,
                          const int* __restrict__ src,
                          const int* __restrict__ dst) {
    int t = blockIdx.x * blockDim.x + threadIdx.x;
    int e = t >> 5;
    if (e >= NE) return;
    const float* __restrict__ h = (SRC_SEL < 0) ? hext : buf_sel(SRC_SEL);
    int lane = t & 31;
    int s = src[e];
    int d = dst[e];
    float ns = g_norm_src[s];
    int c = lane << 2;
    float4 v = *reinterpret_cast<const float4*>(h + (size_t)s * DIM + c);
    if (BN) {
        float4 m  = *reinterpret_cast<const float4*>(g_mean + c);
        float4 rs = *reinterpret_cast<const float4*>(g_rstd + c);
        v.x = (v.x - m.x) * rs.x;
        v.y = (v.y - m.y) * rs.y;
        v.z = (v.z - m.z) * rs.z;
        v.w = (v.w - m.w) * rs.w;
    }
    v.x *= ns; v.y *= ns; v.z *= ns; v.w *= ns;
#if __CUDA_ARCH__ >= 900
    atomicAdd(reinterpret_cast<float4*>(g_buf_agg + (size_t)d * DIM + c), v);
#else
    float* a = g_buf_agg + (size_t)d * DIM + c;
    atomicAdd(a + 0, v.x); atomicAdd(a + 1, v.y);
    atomicAdd(a + 2, v.z); atomicAdd(a + 3, v.w);
#endif
}

// 64-wide spmm: 16 lanes per edge, reads layer-3 g from g_buf_agg, writes out
__global__ void k_spmm64(const int* __restrict__ src,
                         const int* __restrict__ dst,
                         float* __restrict__ out) {
    int t = blockIdx.x * blockDim.x + threadIdx.x;
    int e = t >> 4;
    if (e >= NE) return;
    const float* __restrict__ g = g_buf_agg;
    int l = t & 15;
    int s = src[e];
    int d = dst[e];
    int c = l << 2;
    float4 v = *reinterpret_cast<const float4*>(g + (size_t)s * DC + c);
#if __CUDA_ARCH__ >= 900
    atomicAdd(reinterpret_cast<float4*>(out + (size_t)d * DC + c), v);
#else
    float* a = out + (size_t)d * DC + c;
    atomicAdd(a + 0, v.x); atomicAdd(a + 1, v.y);
    atomicAdd(a + 2, v.z); atomicAdd(a + 3, v.w);
#endif
}

// ---------------- fused GEMM ------------------------------------------------
// out[r,:] = act( (xf(IN[r,:]) * rowscale[r]) @ W + bias ),  K = 128 fixed.
// Block: 64 rows x OUTW cols, 256 threads, thread = 4 rows x (OUTW/16) cols.
template<int OUTW, int IN_SEL, int OUT_SEL, bool BN_IN, bool BIAS_RELU, bool ROWSCALE_DST>
__global__ void __launch_bounds__(256) k_gemm(const float* __restrict__ W,
                                              const float* __restrict__ bias) {
    constexpr int CT = OUTW / 16;       // cols per thread (8 or 4)
    __shared__ float As[64 * 132];      // padded stride to dodge bank conflicts

    const float* __restrict__ A = buf_sel(IN_SEL);
    float* __restrict__ out = buf_sel(OUT_SEL);
    const float* __restrict__ rowscale = ROWSCALE_DST ? g_norm_dst : g_norm_src;

    int rowBase = blockIdx.x * 64;

    #pragma unroll
    for (int it = 0; it < 8; ++it) {
        int idx = threadIdx.x + it * 256;
        int r   = idx >> 5;
        int c   = (idx & 31) << 2;
        int row = rowBase + r;
        float4 v = make_float4(0.f, 0.f, 0.f, 0.f);
        if (row < NN) {
            v = *reinterpret_cast<const float4*>(A + (size_t)row * DIM + c);
            if (BN_IN) {
                float4 m  = *reinterpret_cast<const float4*>(g_mean + c);
                float4 rs = *reinterpret_cast<const float4*>(g_rstd + c);
                v.x = (v.x - m.x) * rs.x;
                v.y = (v.y - m.y) * rs.y;
                v.z = (v.z - m.z) * rs.z;
                v.w = (v.w - m.w) * rs.w;
            }
            float sc = rowscale[row];
            v.x *= sc; v.y *= sc; v.z *= sc; v.w *= sc;
        }
        *reinterpret_cast<float4*>(&As[r * 132 + c]) = v;
    }
    __syncthreads();

    int tr = threadIdx.x >> 4;          // 0..15 (row group)
    int tc = threadIdx.x & 15;          // 0..15 (col group)
    const float* A0 = &As[(tr * 4) * 132];

    float acc[4][CT];
    #pragma unroll
    for (int i = 0; i < 4; ++i)
        #pragma unroll
        for (int j = 0; j < CT; ++j) acc[i][j] = 0.f;

    #pragma unroll 4
    for (int k = 0; k < 128; ++k) {
        float a0 = A0[k];
        float a1 = A0[132 + k];
        float a2 = A0[264 + k];
        float a3 = A0[396 + k];
        const float* wrow = W + k * OUTW + tc * CT;
        float4 w0 = __ldg(reinterpret_cast<const float4*>(wrow));
        float wv[CT];
        wv[0] = w0.x; wv[1] = w0.y; wv[2] = w0.z; wv[3] = w0.w;
        if (CT == 8) {
            float4 w1 = __ldg(reinterpret_cast<const float4*>(wrow + 4));
            wv[4] = w1.x; wv[5] = w1.y; wv[6] = w1.z; wv[7] = w1.w;
        }
        #pragma unroll
        for (int j = 0; j < CT; ++j) {
            acc[0][j] = fmaf(a0, wv[j], acc[0][j]);
            acc[1][j] = fmaf(a1, wv[j], acc[1][j]);
            acc[2][j] = fmaf(a2, wv[j], acc[2][j]);
            acc[3][j] = fmaf(a3, wv[j], acc[3][j]);
        }
    }

    #pragma unroll
    for (int i = 0; i < 4; ++i) {
        int row = rowBase + tr * 4 + i;
        if (row >= NN) continue;
        #pragma unroll
        for (int j0 = 0; j0 < CT; j0 += 4) {
            int col = tc * CT + j0;
            float4 y;
            y.x = acc[i][j0 + 0]; y.y = acc[i][j0 + 1];
            y.z = acc[i][j0 + 2]; y.w = acc[i][j0 + 3];
            if (BIAS_RELU) {
                float4 b = *reinterpret_cast<const float4*>(bias + col);
                y.x = fmaxf(y.x + b.x, 0.f);
                y.y = fmaxf(y.y + b.y, 0.f);
                y.z = fmaxf(y.z + b.z, 0.f);
                y.w = fmaxf(y.w + b.w, 0.f);
            }
            *reinterpret_cast<float4*>(out + (size_t)row * OUTW + col) = y;
        }
    }
}

// ---------------- batchnorm statistics --------------------------------------
__global__ void k_stats() {
    const float* __restrict__ h = g_buf_h;
    __shared__ float ssum[256], ssq[256];
    int col  = threadIdx.x & 127;
    int half = threadIdx.x >> 7;
    float s = 0.f, q = 0.f;
    for (int row = blockIdx.x * 2 + half; row < NN; row += gridDim.x * 2) {
        float v = h[(size_t)row * DIM + col];
        s += v; q += v * v;
    }
    ssum[threadIdx.x] = s; ssq[threadIdx.x] = q;
    __syncthreads();
    if (threadIdx.x < 128) {
        s = ssum[threadIdx.x] + ssum[threadIdx.x + 128];
        q = ssq[threadIdx.x] + ssq[threadIdx.x + 128];
        atomicAdd(&g_sum[col], s);
        atomicAdd(&g_sumsq[col], q);
    }
}

__global__ void k_finalize_stats() {
    int i = threadIdx.x;
    if (i < DIM) {
        float inv = 1.0f / (float)NN;
        float mean = g_sum[i] * inv;
        float var  = fmaxf(g_sumsq[i] * inv - mean * mean, 0.f);
        g_mean[i] = mean;
        g_rstd[i] = rsqrtf(var + BN_EPS);
    }
}

// ---------------- final epilogue: out = out*norm_dst + b2 -------------------
__global__ void k_final_out(float* __restrict__ out, const float* __restrict__ b2) {
    int idx = blockIdx.x * blockDim.x + threadIdx.x;    // over NN*16 float4s
    if (idx >= NN * 16) return;
    int row = idx >> 4;
    int c   = (idx & 15) << 2;
    float nd = g_norm_dst[row];
    float4 v = *reinterpret_cast<float4*>(out + (size_t)row * DC + c);
    float4 b = *reinterpret_cast<const float4*>(b2 + c);
    v.x = fmaf(v.x, nd, b.x);
    v.y = fmaf(v.y, nd, b.y);
    v.z = fmaf(v.z, nd, b.z);
    v.w = fmaf(v.w, nd, b.w);
    *reinterpret_cast<float4*>(out + (size_t)row * DC + c) = v;
}

// ---------------- launch ----------------------------------------------------
extern "C" void kernel_launch(void* const* d_in, const int* in_sizes, int n_in,
                              void* d_out, int out_size) {
    const float* features = (const float*)d_in[0];
    const float* W0 = (const float*)d_in[1];
    const float* b0 = (const float*)d_in[2];
    const float* W1 = (const float*)d_in[3];
    const float* b1 = (const float*)d_in[4];
    const float* W2 = (const float*)d_in[5];
    const float* b2 = (const float*)d_in[6];
    const int* src = (const int*)d_in[7];
    const int* dst = (const int*)d_in[8];
    float* out = (float*)d_out;

    const int TB = 256;
    const int gN    = (NN + TB - 1) / TB;
    const int gE    = (NE + TB - 1) / TB;
    const int gS128 = (NE * 32) / TB;        // 200000
    const int gS64  = (NE * 16) / TB;        // 100000
    const int gGemm = (NN + 63) / 64;        // 1563
    const int gZagg = (NN * DIM / 4 + TB - 1) / TB;
    const int gZout = (NN * DC / 4 + TB - 1) / TB;
    const int gFin  = (NN * 16 + TB - 1) / TB;

    // degrees + norms
    k_init_deg<<<gN, TB>>>();
    k_count<<<gE, TB>>>(src, dst);
    k_norms<<<gN, TB>>>();

    // ---- layer 1: agg = A~(ns*features); h = relu(nd*agg @ W0 + b0) ----
    k_zero_agg<<<gZagg, TB>>>(NN * DIM / 4);
    k_spmm128<-1, false><<<gS128, TB>>>(features, src, dst);
    k_gemm<128, BUF_AGG, BUF_H, false, true, true><<<gGemm, TB>>>(W0, b0);
    k_zero_stats<<<1, 128>>>();
    k_stats<<<512, TB>>>();
    k_finalize_stats<<<1, 128>>>();

    // ---- layer 2: BN folded into gather ----
    k_zero_agg<<<gZagg, TB>>>(NN * DIM / 4);
    k_spmm128<BUF_H, true><<<gS128, TB>>>(nullptr, src, dst);
    k_gemm<128, BUF_AGG, BUF_H, false, true, true><<<gGemm, TB>>>(W1, b1);
    k_zero_stats<<<1, 128>>>();
    k_stats<<<512, TB>>>();
    k_finalize_stats<<<1, 128>>>();

    // ---- layer 3: GEMM first (128->64 halves SpMM traffic), then aggregate --
    // g[N,64] = (BN(h)*norm_src) @ W2, written to g_buf_agg (h stays in g_buf_h)
    k_gemm<64, BUF_H, BUF_AGG, true, false, false><<<gGemm, TB>>>(W2, nullptr);
    k_zero_out<<<gZout, TB>>>(out, NN * DC / 4);
    k_spmm64<<<gS64, TB>>>(src, dst, out);
    k_final_out<<<gFin, TB>>>(out, b2);
}

// round 7
// speedup vs baseline: 1.4747x; 1.4747x over previous
#include <cuda_runtime.h>

#define NN 100000
#define NE 1600000
#define DIM 128
#define DC 64
#define BN_EPS 1e-5f
#define SCAN_B 1024
#define NB ((NN + SCAN_B - 1) / SCAN_B)   // 98

// ---------------- scratch (device globals; no allocation allowed) ----------
__device__ float g_buf_agg[NN * DIM];   // aggregated features / layer-3 g [N,64]
__device__ float g_buf_h[NN * DIM];     // hidden activations
__device__ float g_norm_src[NN];
__device__ float g_norm_dst[NN];
__device__ int   g_deg_out[NN];
__device__ int   g_deg_in[NN];
__device__ int   g_off[NN];             // CSR row offsets (exclusive scan of deg_in)
__device__ int   g_cursor[NN];          // fill cursors
__device__ int   g_csr_src[NE];         // CSR column indices (source node per in-edge)
__device__ int   g_blocksum[NB];
__device__ int   g_blockoff[NB];
__device__ float g_sum[DIM];
__device__ float g_sumsq[DIM];
__device__ float g_mean[DIM];
__device__ float g_rstd[DIM];

#define BUF_AGG 0
#define BUF_H   1
__device__ __forceinline__ const float* buf_sel(int s) {
    return (s == BUF_AGG) ? g_buf_agg : g_buf_h;
}
__device__ __forceinline__ float* buf_sel_w(int s) {
    return (s == BUF_AGG) ? g_buf_agg : g_buf_h;
}

// ---------------- setup: zero counters --------------------------------------
__global__ void k_zero_all() {
    int i = blockIdx.x * blockDim.x + threadIdx.x;
    if (i < NN) { g_deg_out[i] = 0; g_deg_in[i] = 0; g_cursor[i] = 0; }
}

__global__ void k_count(const int* __restrict__ src, const int* __restrict__ dst) {
    int e = blockIdx.x * blockDim.x + threadIdx.x;
    if (e < NE) {
        atomicAdd(&g_deg_out[src[e]], 1);
        atomicAdd(&g_deg_in[dst[e]], 1);
    }
}

__global__ void k_norms() {
    int i = blockIdx.x * blockDim.x + threadIdx.x;
    if (i < NN) {
        g_norm_src[i] = rsqrtf(fmaxf((float)g_deg_out[i], 1.0f));
        g_norm_dst[i] = rsqrtf(fmaxf((float)g_deg_in[i], 1.0f));
    }
}

// ---------------- CSR build: scan + fill ------------------------------------
__global__ void __launch_bounds__(SCAN_B) k_scan_local() {
    __shared__ int s[SCAN_B];
    int i = blockIdx.x * SCAN_B + threadIdx.x;
    int x = (i < NN) ? g_deg_in[i] : 0;
    s[threadIdx.x] = x;
    __syncthreads();
    #pragma unroll
    for (int off = 1; off < SCAN_B; off <<= 1) {
        int v = (threadIdx.x >= off) ? s[threadIdx.x - off] : 0;
        __syncthreads();
        s[threadIdx.x] += v;
        __syncthreads();
    }
    if (i < NN) g_off[i] = s[threadIdx.x] - x;   // exclusive
    if (threadIdx.x == SCAN_B - 1) g_blocksum[blockIdx.x] = s[SCAN_B - 1];
}

__global__ void k_scan_block() {
    __shared__ int s[NB];
    if (threadIdx.x < NB) s[threadIdx.x] = g_blocksum[threadIdx.x];
    __syncthreads();
    if (threadIdx.x == 0) {
        int acc = 0;
        for (int b = 0; b < NB; ++b) { int v = s[b]; s[b] = acc; acc += v; }
    }
    __syncthreads();
    if (threadIdx.x < NB) g_blockoff[threadIdx.x] = s[threadIdx.x];
}

__global__ void k_scan_add() {
    int i = blockIdx.x * blockDim.x + threadIdx.x;
    if (i < NN) g_off[i] += g_blockoff[i >> 10];
}

__global__ void k_fill_csr(const int* __restrict__ src, const int* __restrict__ dst) {
    int e = blockIdx.x * blockDim.x + threadIdx.x;
    if (e < NE) {
        int d = dst[e];
        int pos = atomicAdd(&g_cursor[d], 1);
        g_csr_src[g_off[d] + pos] = src[e];
    }
}

// ---------------- pull aggregation (128 wide) --------------------------------
// warp per dst node, 32 lanes x float4. Writes acc * norm_dst to g_buf_agg.
// BN folded algebraically: sum ns*(v-m)*rs = rs*(sum ns*v - m*sum ns).
template<int SRC_SEL, bool BN>
__global__ void __launch_bounds__(256) k_pull128(const float* __restrict__ hext) {
    int t = blockIdx.x * blockDim.x + threadIdx.x;
    int node = t >> 5;
    if (node >= NN) return;
    const float* __restrict__ h = (SRC_SEL < 0) ? hext : buf_sel(SRC_SEL);
    int lane = t & 31;
    int c = lane << 2;
    int start = g_off[node];
    int n = g_deg_in[node];

    float4 a0 = make_float4(0.f, 0.f, 0.f, 0.f);
    float4 a1 = make_float4(0.f, 0.f, 0.f, 0.f);
    float sns = 0.f;

    int j = 0;
    for (; j + 2 <= n; j += 2) {
        int s0 = __ldg(&g_csr_src[start + j]);
        int s1 = __ldg(&g_csr_src[start + j + 1]);
        float n0 = __ldg(&g_norm_src[s0]);
        float n1 = __ldg(&g_norm_src[s1]);
        float4 v0 = *reinterpret_cast<const float4*>(h + (size_t)s0 * DIM + c);
        float4 v1 = *reinterpret_cast<const float4*>(h + (size_t)s1 * DIM + c);
        a0.x = fmaf(n0, v0.x, a0.x); a0.y = fmaf(n0, v0.y, a0.y);
        a0.z = fmaf(n0, v0.z, a0.z); a0.w = fmaf(n0, v0.w, a0.w);
        a1.x = fmaf(n1, v1.x, a1.x); a1.y = fmaf(n1, v1.y, a1.y);
        a1.z = fmaf(n1, v1.z, a1.z); a1.w = fmaf(n1, v1.w, a1.w);
        if (BN) sns += n0 + n1;
    }
    if (j < n) {
        int s0 = __ldg(&g_csr_src[start + j]);
        float n0 = __ldg(&g_norm_src[s0]);
        float4 v0 = *reinterpret_cast<const float4*>(h + (size_t)s0 * DIM + c);
        a0.x = fmaf(n0, v0.x, a0.x); a0.y = fmaf(n0, v0.y, a0.y);
        a0.z = fmaf(n0, v0.z, a0.z); a0.w = fmaf(n0, v0.w, a0.w);
        if (BN) sns += n0;
    }
    a0.x += a1.x; a0.y += a1.y; a0.z += a1.z; a0.w += a1.w;

    if (BN) {
        float4 m  = *reinterpret_cast<const float4*>(g_mean + c);
        float4 rs = *reinterpret_cast<const float4*>(g_rstd + c);
        a0.x = (a0.x - m.x * sns) * rs.x;
        a0.y = (a0.y - m.y * sns) * rs.y;
        a0.z = (a0.z - m.z * sns) * rs.z;
        a0.w = (a0.w - m.w * sns) * rs.w;
    }
    float nd = g_norm_dst[node];
    a0.x *= nd; a0.y *= nd; a0.z *= nd; a0.w *= nd;
    *reinterpret_cast<float4*>(g_buf_agg + (size_t)node * DIM + c) = a0;
}

// ---------------- pull aggregation (64 wide, final layer) --------------------
// half-warp per dst node (16 lanes x float4). out = acc * norm_dst + b2.
// g rows already include norm_src (folded into the preceding GEMM).
__global__ void __launch_bounds__(256) k_pull64(float* __restrict__ out,
                                                const float* __restrict__ b2) {
    int t = blockIdx.x * blockDim.x + threadIdx.x;
    int node = t >> 4;
    if (node >= NN) return;
    const float* __restrict__ g = g_buf_agg;
    int lane = t & 15;
    int c = lane << 2;
    int start = g_off[node];
    int n = g_deg_in[node];

    float4 a0 = make_float4(0.f, 0.f, 0.f, 0.f);
    float4 a1 = make_float4(0.f, 0.f, 0.f, 0.f);

    int j = 0;
    for (; j + 2 <= n; j += 2) {
        int s0 = __ldg(&g_csr_src[start + j]);
        int s1 = __ldg(&g_csr_src[start + j + 1]);
        float4 v0 = *reinterpret_cast<const float4*>(g + (size_t)s0 * DC + c);
        float4 v1 = *reinterpret_cast<const float4*>(g + (size_t)s1 * DC + c);
        a0.x += v0.x; a0.y += v0.y; a0.z += v0.z; a0.w += v0.w;
        a1.x += v1.x; a1.y += v1.y; a1.z += v1.z; a1.w += v1.w;
    }
    if (j < n) {
        int s0 = __ldg(&g_csr_src[start + j]);
        float4 v0 = *reinterpret_cast<const float4*>(g + (size_t)s0 * DC + c);
        a0.x += v0.x; a0.y += v0.y; a0.z += v0.z; a0.w += v0.w;
    }
    a0.x += a1.x; a0.y += a1.y; a0.z += a1.z; a0.w += a1.w;

    float nd = g_norm_dst[node];
    float4 b = *reinterpret_cast<const float4*>(b2 + c);
    a0.x = fmaf(a0.x, nd, b.x);
    a0.y = fmaf(a0.y, nd, b.y);
    a0.z = fmaf(a0.z, nd, b.z);
    a0.w = fmaf(a0.w, nd, b.w);
    *reinterpret_cast<float4*>(out + (size_t)node * DC + c) = a0;
}

// ---------------- fused GEMM ------------------------------------------------
// out[r,:] = act( (xf(IN[r,:]) * scale) @ W + bias ),  K = 128 fixed.
// SCALE_MODE: 0 = none, 1 = norm_src (layer-3 pre-aggregation fold)
// Block: 64 rows x OUTW cols, 256 threads, thread = 4 rows x (OUTW/16) cols.
template<int OUTW, int IN_SEL, int OUT_SEL, bool BN_IN, bool BIAS_RELU, int SCALE_MODE>
__global__ void __launch_bounds__(256) k_gemm(const float* __restrict__ W,
                                              const float* __restrict__ bias) {
    constexpr int CT = OUTW / 16;       // cols per thread (8 or 4)
    __shared__ float As[64 * 132];      // padded stride to dodge bank conflicts

    const float* __restrict__ A = buf_sel(IN_SEL);
    float* __restrict__ out = buf_sel_w(OUT_SEL);

    int rowBase = blockIdx.x * 64;

    #pragma unroll
    for (int it = 0; it < 8; ++it) {
        int idx = threadIdx.x + it * 256;
        int r   = idx >> 5;
        int c   = (idx & 31) << 2;
        int row = rowBase + r;
        float4 v = make_float4(0.f, 0.f, 0.f, 0.f);
        if (row < NN) {
            v = *reinterpret_cast<const float4*>(A + (size_t)row * DIM + c);
            if (BN_IN) {
                float4 m  = *reinterpret_cast<const float4*>(g_mean + c);
                float4 rs = *reinterpret_cast<const float4*>(g_rstd + c);
                v.x = (v.x - m.x) * rs.x;
                v.y = (v.y - m.y) * rs.y;
                v.z = (v.z - m.z) * rs.z;
                v.w = (v.w - m.w) * rs.w;
            }
            if (SCALE_MODE == 1) {
                float sc = g_norm_src[row];
                v.x *= sc; v.y *= sc; v.z *= sc; v.w *= sc;
            }
        }
        *reinterpret_cast<float4*>(&As[r * 132 + c]) = v;
    }
    __syncthreads();

    int tr = threadIdx.x >> 4;          // 0..15 (row group)
    int tc = threadIdx.x & 15;          // 0..15 (col group)
    const float* A0 = &As[(tr * 4) * 132];

    float acc[4][CT];
    #pragma unroll
    for (int i = 0; i < 4; ++i)
        #pragma unroll
        for (int j = 0; j < CT; ++j) acc[i][j] = 0.f;

    #pragma unroll 4
    for (int k = 0; k < 128; ++k) {
        float a0 = A0[k];
        float a1 = A0[132 + k];
        float a2 = A0[264 + k];
        float a3 = A0[396 + k];
        const float* wrow = W + k * OUTW + tc * CT;
        float4 w0 = __ldg(reinterpret_cast<const float4*>(wrow));
        float wv[CT];
        wv[0] = w0.x; wv[1] = w0.y; wv[2] = w0.z; wv[3] = w0.w;
        if (CT == 8) {
            float4 w1 = __ldg(reinterpret_cast<const float4*>(wrow + 4));
            wv[4] = w1.x; wv[5] = w1.y; wv[6] = w1.z; wv[7] = w1.w;
        }
        #pragma unroll
        for (int j = 0; j < CT; ++j) {
            acc[0][j] = fmaf(a0, wv[j], acc[0][j]);
            acc[1][j] = fmaf(a1, wv[j], acc[1][j]);
            acc[2][j] = fmaf(a2, wv[j], acc[2][j]);
            acc[3][j] = fmaf(a3, wv[j], acc[3][j]);
        }
    }

    #pragma unroll
    for (int i = 0; i < 4; ++i) {
        int row = rowBase + tr * 4 + i;
        if (row >= NN) continue;
        #pragma unroll
        for (int j0 = 0; j0 < CT; j0 += 4) {
            int col = tc * CT + j0;
            float4 y;
            y.x = acc[i][j0 + 0]; y.y = acc[i][j0 + 1];
            y.z = acc[i][j0 + 2]; y.w = acc[i][j0 + 3];
            if (BIAS_RELU) {
                float4 b = *reinterpret_cast<const float4*>(bias + col);
                y.x = fmaxf(y.x + b.x, 0.f);
                y.y = fmaxf(y.y + b.y, 0.f);
                y.z = fmaxf(y.z + b.z, 0.f);
                y.w = fmaxf(y.w + b.w, 0.f);
            }
            *reinterpret_cast<float4*>(out + (size_t)row * OUTW + col) = y;
        }
    }
}

// ---------------- batchnorm statistics --------------------------------------
__global__ void k_zero_stats() {
    int i = threadIdx.x;
    if (i < DIM) { g_sum[i] = 0.f; g_sumsq[i] = 0.f; }
}

__global__ void k_stats() {
    const float* __restrict__ h = g_buf_h;
    __shared__ float ssum[256], ssq[256];
    int col  = threadIdx.x & 127;
    int half = threadIdx.x >> 7;
    float s = 0.f, q = 0.f;
    for (int row = blockIdx.x * 2 + half; row < NN; row += gridDim.x * 2) {
        float v = h[(size_t)row * DIM + col];
        s += v; q += v * v;
    }
    ssum[threadIdx.x] = s; ssq[threadIdx.x] = q;
    __syncthreads();
    if (threadIdx.x < 128) {
        s = ssum[threadIdx.x] + ssum[threadIdx.x + 128];
        q = ssq[threadIdx.x] + ssq[threadIdx.x + 128];
        atomicAdd(&g_sum[col], s);
        atomicAdd(&g_sumsq[col], q);
    }
}

__global__ void k_finalize_stats() {
    int i = threadIdx.x;
    if (i < DIM) {
        float inv = 1.0f / (float)NN;
        float mean = g_sum[i] * inv;
        float var  = fmaxf(g_sumsq[i] * inv - mean * mean, 0.f);
        g_mean[i] = mean;
        g_rstd[i] = rsqrtf(var + BN_EPS);
    }
}

// ---------------- launch ----------------------------------------------------
extern "C" void kernel_launch(void* const* d_in, const int* in_sizes, int n_in,
                              void* d_out, int out_size) {
    const float* features = (const float*)d_in[0];
    const float* W0 = (const float*)d_in[1];
    const float* b0 = (const float*)d_in[2];
    const float* W1 = (const float*)d_in[3];
    const float* b1 = (const float*)d_in[4];
    const float* W2 = (const float*)d_in[5];
    const float* b2 = (const float*)d_in[6];
    const int* src = (const int*)d_in[7];
    const int* dst = (const int*)d_in[8];
    float* out = (float*)d_out;

    const int TB = 256;
    const int gN     = (NN + TB - 1) / TB;
    const int gE     = (NE + TB - 1) / TB;
    const int gPull  = (NN * 32 + TB - 1) / TB;   // 12500 (warp per node)
    const int gPull64= (NN * 16 + TB - 1) / TB;   // 6250 (half-warp per node)
    const int gGemm  = (NN + 63) / 64;            // 1563

    // ---- setup: degrees, norms, CSR ----
    k_zero_all<<<gN, TB>>>();
    k_count<<<gE, TB>>>(src, dst);
    k_norms<<<gN, TB>>>();
    k_scan_local<<<NB, SCAN_B>>>();
    k_scan_block<<<1, 128>>>();
    k_scan_add<<<gN, TB>>>();
    k_fill_csr<<<gE, TB>>>(src, dst);

    // ---- layer 1: agg = nd * A~(ns*features); h = relu(agg @ W0 + b0) ----
    k_pull128<-1, false><<<gPull, TB>>>(features);
    k_gemm<128, BUF_AGG, BUF_H, false, true, 0><<<gGemm, TB>>>(W0, b0);
    k_zero_stats<<<1, 128>>>();
    k_stats<<<512, TB>>>();
    k_finalize_stats<<<1, 128>>>();

    // ---- layer 2: BN folded into pull ----
    k_pull128<BUF_H, true><<<gPull, TB>>>(nullptr);
    k_gemm<128, BUF_AGG, BUF_H, false, true, 0><<<gGemm, TB>>>(W1, b1);
    k_zero_stats<<<1, 128>>>();
    k_stats<<<512, TB>>>();
    k_finalize_stats<<<1, 128>>>();

    // ---- layer 3: GEMM first (128->64), then pull with nd+bias epilogue ----
    // g[N,64] = (BN(h) * norm_src) @ W2  -> g_buf_agg
    k_gemm<64, BUF_H, BUF_AGG, true, false, 1><<<gGemm, TB>>>(W2, nullptr);
    k_pull64<<<gPull64, TB>>>(out, b2);
}